// round 15
// baseline (speedup 1.0000x reference)
#include <cuda_runtime.h>
#include <cuda_fp16.h>
#include <cstdint>
#include <math.h>

#define B_    16
#define CIN   512
#define COUT  512
#define QT    137              // legacy q tiles of 128 (NQPAD base)
#define NQPAD (QT*128)         // 17536 padded position rows
#define NQV   (16*1089)        // 17424 valid positions (16 x 33x33 cells)
#define PADR  64               // leading zero rows per chunk (for shift offsets)
#define NR    (NQPAD + PADR)   // physical rows per chunk
#define IDX(p,q) ((size_t)(p)*NQV + (q))
#define STG   24576u           // stage bytes: A 8KB + B 16KB
#define RS    748              // fir smem row stride per co: 11*68 floats
#define FIRSM (32*RS*4)        // 95.7 KB

// ------------------------- device scratch -------------------------
__device__ float g_style[B_*CIN];
__device__ float g_wsq[COUT*CIN];
__device__ float g_dcoef[B_*COUT];
__device__ __align__(128) __half g_Xs[(size_t)8*NR*64];      // [chunk][PADR+q][64] swizzled fp16
__device__ __align__(128) __half g_Ws[(size_t)9*8*512*64];   // [tap][chunk][co][64] swizzled fp16
__device__ __align__(16)  __half g_yp[(size_t)4*NQV*512];    // [parity][q][co] fp16

__constant__ int c_taps[4][4] = {{0,2,6,8},{1,7,0,0},{3,5,0,0},{4,0,0,0}};
__constant__ int c_off [4][4] = {{0,1,33,34},{0,33,0,0},{0,1,0,0},{0,0,0,0}};
__constant__ int c_nkb [4]    = {4,2,2,1};

// ------------------------- helpers -------------------------
__device__ __forceinline__ uint32_t smem_u32(const void* p) {
    uint32_t a;
    asm("{ .reg .u64 t; cvta.to.shared.u64 t, %1; cvt.u32.u64 %0, t; }" : "=r"(a) : "l"(p));
    return a;
}
__device__ __forceinline__ void cp16(uint32_t s, const void* g) {
    asm volatile("cp.async.cg.shared.global [%0], [%1], 16;" :: "r"(s), "l"(g) : "memory");
}
__device__ __forceinline__ void ldsm4(uint32_t& r0, uint32_t& r1, uint32_t& r2, uint32_t& r3,
                                      uint32_t addr) {
    asm volatile("ldmatrix.sync.aligned.m8n8.x4.shared.b16 {%0,%1,%2,%3}, [%4];"
                 : "=r"(r0), "=r"(r1), "=r"(r2), "=r"(r3) : "r"(addr));
}
__device__ __forceinline__ void mma16816(float* c, const uint32_t* a, const uint32_t* b) {
    asm volatile("mma.sync.aligned.m16n8k16.row.col.f32.f16.f16.f32 "
                 "{%0,%1,%2,%3}, {%4,%5,%6,%7}, {%8,%9}, {%0,%1,%2,%3};"
                 : "+f"(c[0]), "+f"(c[1]), "+f"(c[2]), "+f"(c[3])
                 : "r"(a[0]), "r"(a[1]), "r"(a[2]), "r"(a[3]), "r"(b[0]), "r"(b[1]));
}

// ------------------------- [1] W build + wsq (fused) -------------------------
__global__ void __launch_bounds__(256) k_wbuild(const float* __restrict__ cw) {
    int c = blockIdx.y;
    int co = blockIdx.x * 4 + (threadIdx.x >> 6);
    int kp = threadIdx.x & 63;
    int k = kp ^ ((co & 7) << 3);
    const float* p = cw + ((size_t)co * 512 + c * 64 + k) * 9;
    float s = 0.f;
    #pragma unroll
    for (int tap = 0; tap < 9; tap++) {
        float w = p[tap];
        s += w * w;
        g_Ws[((size_t)(tap * 8 + c) * 512 + co) * 64 + kp] = __float2half_rn(w);
    }
    g_wsq[co * 512 + c * 64 + k] = s;
}

// ------------------------- [2] style -------------------------
__global__ void k_style(const float* __restrict__ wl, const float* __restrict__ aw,
                        const float* __restrict__ ab) {
    int w = blockIdx.x * 8 + (threadIdx.x >> 5), lane = threadIdx.x & 31;
    int b = w >> 9, ci = w & 511;
    const float* wlp = wl + b * 512;
    const float* awp = aw + (size_t)ci * 512;
    float s = 0.f;
    #pragma unroll 4
    for (int k = lane; k < 512; k += 32) s += wlp[k] * awp[k];
    #pragma unroll
    for (int o = 16; o; o >>= 1) s += __shfl_down_sync(0xffffffffu, s, o);
    if (lane == 0) g_style[w] = s * 0.04419417382415922f + ab[ci];
}

// ------------------------- [3] X prep -------------------------
__global__ void __launch_bounds__(256) k_xprep(const float* __restrict__ x) {
    const int b = blockIdx.z, c = blockIdx.y;
    const int tid = threadIdx.x;

    if (blockIdx.x == 16) {        // zero rows: ring (65/batch), pad (b==0), tail (b==15)
        int nrow = 65 + (b == 0 ? PADR : 0) + (b == 15 ? (NQPAD - NQV) : 0);
        for (int e = tid; e < nrow * 64; e += 256) {
            int ri = e >> 6, kp = e & 63;
            size_t prow;
            if (ri < 33) {
                prow = (size_t)c * NR + PADR + b * 1089 + 32 * 33 + ri;
            } else if (ri < 65) {
                prow = (size_t)c * NR + PADR + b * 1089 + (ri - 33) * 33 + 32;
            } else if (b == 0 && ri < 65 + PADR) {
                prow = (size_t)c * NR + (ri - 65);
            } else {
                int rj = ri - 65 - (b == 0 ? PADR : 0);
                prow = (size_t)c * NR + PADR + NQV + rj;
            }
            g_Xs[prow * 64 + kp] = __float2half_rn(0.f);
        }
        return;
    }

    __shared__ float t[64][65];
    const int px0 = blockIdx.x * 64;
    for (int e = tid; e < 4096; e += 256) {
        int ci_l = e >> 6, px = e & 63;
        t[ci_l][px] = x[(((size_t)b * 512 + c * 64 + ci_l) << 10) + px0 + px]
                    * g_style[b * 512 + c * 64 + ci_l];
    }
    __syncthreads();
    for (int e = tid; e < 2048; e += 256) {
        int px_l = e >> 5, kpp = e & 31;
        int pix = px0 + px_l;
        int m = pix >> 5, n = pix & 31;
        int q = b * 1089 + m * 33 + n;
        int k0 = (2 * kpp) ^ ((q & 7) << 3);
        size_t d = ((size_t)c * NR + PADR + q) * 64 + 2 * kpp;
        *(__half2*)&g_Xs[d] = __half2(__float2half_rn(t[k0][px_l]),
                                      __float2half_rn(t[k0 + 1][px_l]));
    }
}

// ------------------------- [4] GEMM (64q x 128co, 3 CTA/SM, fp16 mma f32-accum) --------
__global__ void __launch_bounds__(256, 3) k_gemm() {
    extern __shared__ __align__(1024) char sm[];   // 3 stages x (A 8KB | B 16KB)
    const int tid = threadIdx.x;
    const int p = blockIdx.z, by = blockIdx.y;
    const int qbase = blockIdx.x * 64;
    const int ntap = c_nkb[p];
    const int NKB = ntap * 8;
    const int wid = tid >> 5, lane = tid & 31;
    const int wm = wid & 1, wn = wid >> 1;         // 2x4 warps -> 32q x 32co each
    const uint32_t sbase = smem_u32(sm);

    float acc[2][4][4];
    #pragma unroll
    for (int mt = 0; mt < 2; mt++)
        #pragma unroll
        for (int nt = 0; nt < 4; nt++)
            #pragma unroll
            for (int r = 0; r < 4; r++) acc[mt][nt][r] = 0.f;

    const int arow = lane & 15;
    const uint32_t acolhi = (uint32_t)(lane >> 4) << 4;
    uint32_t aoff[2];
    #pragma unroll
    for (int mt = 0; mt < 2; mt++) aoff[mt] = (wm * 32 + mt * 16 + arow) * 128;

    const int bnl = (lane & 7) + ((lane >> 4) << 3);
    const uint32_t bhi = (uint32_t)((lane >> 3) & 1) << 4;
    const uint32_t bsw = (uint32_t)(lane & 7) << 4;
    uint32_t boff[2];
    #pragma unroll
    for (int g = 0; g < 2; g++) boff[g] = (wn * 32 + g * 16 + bnl) * 128;

    auto stage_load = [&](int s, int kb) {
        int c = kb & 7, ti = kb >> 3;
        int off = c_off[p][ti], tap = c_taps[p][ti];
        const char* Ag = (const char*)(g_Xs + ((size_t)c * NR + PADR + qbase - off) * 64)
                       + tid * 32;
        const char* Bg = (const char*)(g_Ws + ((size_t)(tap * 8 + c) * 512 + by * 128) * 64)
                       + tid * 64;
        uint32_t sa = sbase + s * STG;
        cp16(sa + tid * 32,      Ag);
        cp16(sa + tid * 32 + 16, Ag + 16);
        #pragma unroll
        for (int i = 0; i < 4; i++)
            cp16(sa + 8192 + tid * 64 + i * 16, Bg + i * 16);
        asm volatile("cp.async.commit_group;" ::: "memory");
    };

    stage_load(0, 0);
    if (NKB > 1) stage_load(1, 1);
    else asm volatile("cp.async.commit_group;" ::: "memory");

    for (int kb = 0; kb < NKB; kb++) {
        int s = kb % 3;
        asm volatile("cp.async.wait_group 1;" ::: "memory");
        __syncthreads();
        if (kb + 2 < NKB) stage_load((kb + 2) % 3, kb + 2);
        else asm volatile("cp.async.commit_group;" ::: "memory");

        int off = c_off[p][kb >> 3];
        uint32_t asw = (uint32_t)(((arow - off) & 7) << 4);
        uint32_t Abase = sbase + s * STG;
        uint32_t Bbase = Abase + 8192;
        #pragma unroll
        for (int ks = 0; ks < 4; ks++) {
            uint32_t A[2][4], Bf[4][2];
            uint32_t ak = (((uint32_t)ks << 5) | acolhi) ^ asw;
            #pragma unroll
            for (int mt = 0; mt < 2; mt++)
                ldsm4(A[mt][0], A[mt][1], A[mt][2], A[mt][3], Abase + aoff[mt] + ak);
            uint32_t bk = (((uint32_t)ks << 5) | bhi) ^ bsw;
            #pragma unroll
            for (int g = 0; g < 2; g++)
                ldsm4(Bf[2*g][0], Bf[2*g][1], Bf[2*g+1][0], Bf[2*g+1][1], Bbase + boff[g] + bk);
            #pragma unroll
            for (int mt = 0; mt < 2; mt++)
                #pragma unroll
                for (int nt = 0; nt < 4; nt++)
                    mma16816(acc[mt][nt], A[mt], Bf[nt]);
        }
    }

    #pragma unroll
    for (int mt = 0; mt < 2; mt++) {
        int r0 = qbase + wm * 32 + mt * 16 + (lane >> 2);
        #pragma unroll
        for (int nt = 0; nt < 4; nt++) {
            int co = by * 128 + wn * 32 + nt * 8 + ((lane & 3) << 1);
            if (r0 < NQV)
                *(__half2*)&g_yp[IDX(p, r0) * 512 + co] =
                    __floats2half2_rn(acc[mt][nt][0], acc[mt][nt][1]);
            if (r0 + 8 < NQV)
                *(__half2*)&g_yp[IDX(p, r0 + 8) * 512 + co] =
                    __floats2half2_rn(acc[mt][nt][2], acc[mt][nt][3]);
        }
    }
}

// ------------------------- [5] dcoef -------------------------
__global__ void k_dcoef() {
    int w = blockIdx.x * 8 + (threadIdx.x >> 5), lane = threadIdx.x & 31;
    int b = w >> 9, co = w & 511;
    float s = 0.f;
    #pragma unroll 4
    for (int ci = lane; ci < 512; ci += 32) {
        float st = g_style[b * 512 + ci];
        s += g_wsq[co * 512 + ci] * st * st;
    }
    #pragma unroll
    for (int o = 16; o; o >>= 1) s += __shfl_down_sync(0xffffffffu, s, o);
    if (lane == 0) g_dcoef[w] = rsqrtf(s + 1e-8f);
}

// ------------------------- [6] FIR + demod + noise + bias + lrelu + clamp ----------------
__global__ void __launch_bounds__(512) k_fir(const float* __restrict__ noise,
                                             const float* __restrict__ nstr,
                                             const float* __restrict__ bias,
                                             float* __restrict__ out) {
    extern __shared__ float ys[];                 // 32 co x RS
    const int u0 = blockIdx.x * 8;
    const int co0 = blockIdx.y * 32;
    const int b = blockIdx.z;
    const int tid = threadIdx.x;

    for (int e = tid; e < 11 * 67 * 32; e += 512) {
        int co_l = e & 31, t = e >> 5;
        int cc = t % 67;
        int rr = t / 67 + u0 - 1;
        int vccol = cc - 1;
        float v = 0.f;
        if ((unsigned)rr <= 64u && (unsigned)vccol <= 64u) {
            int pp = ((rr & 1) << 1) | (vccol & 1);
            int q = b * 1089 + (rr >> 1) * 33 + (vccol >> 1);
            v = __half2float(g_yp[IDX(pp, q) * 512 + co0 + co_l]);
        }
        ys[co_l * RS + (t / 67) * 68 + cc] = v;
    }
    __syncthreads();

    const int co_l = tid >> 4;                    // 0..31
    const int v0 = (tid & 15) * 4;                // lanes vary v -> coalesced
    const float fw[4] = {0.25f, 0.75f, 0.75f, 0.25f};
    const float dc = g_dcoef[b * 512 + co0 + co_l];
    const float ns = nstr[0];
    const float bi = bias[co0 + co_l];
    const float4* yrow = (const float4*)(ys + co_l * RS);

    float rs[11][4];
    #pragma unroll
    for (int r = 0; r < 11; r++) {
        float4 a = yrow[(r * 68 + v0) >> 2];
        float4 bq = yrow[(r * 68 + v0 + 4) >> 2];
        float w[8] = {a.x, a.y, a.z, a.w, bq.x, bq.y, bq.z, bq.w};
        #pragma unroll
        for (int j = 0; j < 4; j++)
            rs[r][j] = fmaf(fw[0], w[j], fmaf(fw[1], w[j+1],
                       fmaf(fw[2], w[j+2], fw[3] * w[j+3])));
    }

    #pragma unroll
    for (int ul = 0; ul < 8; ul++) {
        const int u = u0 + ul;
        const float4 nz = *(const float4*)&noise[(b << 12) + u * 64 + v0];
        const float nzv[4] = {nz.x, nz.y, nz.z, nz.w};
        float4 o4;
        float* op = &o4.x;
        #pragma unroll
        for (int j = 0; j < 4; j++) {
            float accv = fmaf(fw[0], rs[ul][j], fmaf(fw[1], rs[ul+1][j],
                         fmaf(fw[2], rs[ul+2][j], fw[3] * rs[ul+3][j])));
            float val = fmaf(nzv[j], ns, accv * dc) + bi;
            val = (val > 0.f ? val : 0.2f * val) * 1.4142135623730951f;
            val = fminf(fmaxf(val, -256.f), 256.f);
            op[j] = val;
        }
        *(float4*)&out[(((size_t)b * 512 + co0 + co_l) * 64 + u) * 64 + v0] = o4;
    }
}

// ------------------------- launch -------------------------
extern "C" void kernel_launch(void* const* d_in, const int* in_sizes, int n_in,
                              void* d_out, int out_size) {
    const float* x     = (const float*)d_in[0];
    const float* wl    = (const float*)d_in[1];
    const float* aw    = (const float*)d_in[2];
    const float* ab    = (const float*)d_in[3];
    const float* cw    = (const float*)d_in[4];
    const float* noise = (const float*)d_in[5];
    const float* nstr  = (const float*)d_in[6];
    const float* bias  = (const float*)d_in[7];
    float* out = (float*)d_out;

    cudaFuncSetAttribute(k_gemm, cudaFuncAttributeMaxDynamicSharedMemorySize, 3 * STG);
    cudaFuncSetAttribute(k_fir, cudaFuncAttributeMaxDynamicSharedMemorySize, FIRSM);

    k_wbuild<<<dim3(128, 8), 256>>>(cw);                    // 1 (wsq fused)
    k_style<<<1024, 256>>>(wl, aw, ab);                     // 2
    k_xprep<<<dim3(17, 8, B_), 256>>>(x);                   // 3
    k_gemm<<<dim3(NQPAD / 64, 4, 4), 256, 3 * STG>>>();     // 4  <- profiled slot
    k_dcoef<<<1024, 256>>>();                               // 5
    k_fir<<<dim3(8, 16, B_), 512, FIRSM>>>(noise, nstr, bias, out);  // 6
}

// round 16
// speedup vs baseline: 1.1398x; 1.1398x over previous
#include <cuda_runtime.h>
#include <cuda_fp16.h>
#include <cstdint>
#include <math.h>

#define B_    16
#define CIN   512
#define COUT  512
#define QT    137              // q tiles of 128
#define NQPAD (QT*128)         // 17536 padded position rows
#define NQV   (16*1089)        // 17424 valid positions (16 x 33x33 cells)
#define PADR  64               // leading zero rows per chunk (for shift offsets)
#define NR    (NQPAD + PADR)   // physical rows per chunk
#define IDX(p,q) ((size_t)(p)*NQV + (q))
#define STG   32768u           // stage bytes: A 16KB + B 16KB
#define RS    748              // fir smem row stride per co: 11*68 floats
#define FIRSM (32*RS*4)        // 95.7 KB

// ------------------------- device scratch -------------------------
__device__ float g_style[B_*CIN];
__device__ float g_wsq[COUT*CIN];
__device__ float g_dcoef[B_*COUT];
__device__ __align__(128) __half g_Xs[(size_t)8*NR*64];      // [chunk][PADR+q][64] swizzled fp16
__device__ __align__(128) __half g_Ws[(size_t)9*8*512*64];   // [tap][chunk][co][64] swizzled fp16
__device__ __align__(16)  __half g_yp[(size_t)4*NQV*512];    // [parity][q][co] fp16

__constant__ int c_taps[4][4] = {{0,2,6,8},{1,7,0,0},{3,5,0,0},{4,0,0,0}};
__constant__ int c_off [4][4] = {{0,1,33,34},{0,33,0,0},{0,1,0,0},{0,0,0,0}};
__constant__ int c_nkb [4]    = {4,2,2,1};

// ------------------------- helpers -------------------------
__device__ __forceinline__ uint32_t smem_u32(const void* p) {
    uint32_t a;
    asm("{ .reg .u64 t; cvta.to.shared.u64 t, %1; cvt.u32.u64 %0, t; }" : "=r"(a) : "l"(p));
    return a;
}
__device__ __forceinline__ void cp16(uint32_t s, const void* g) {
    asm volatile("cp.async.cg.shared.global [%0], [%1], 16;" :: "r"(s), "l"(g) : "memory");
}
__device__ __forceinline__ void ldsm4(uint32_t& r0, uint32_t& r1, uint32_t& r2, uint32_t& r3,
                                      uint32_t addr) {
    asm volatile("ldmatrix.sync.aligned.m8n8.x4.shared.b16 {%0,%1,%2,%3}, [%4];"
                 : "=r"(r0), "=r"(r1), "=r"(r2), "=r"(r3) : "r"(addr));
}
__device__ __forceinline__ void mma16816(float* c, const uint32_t* a, const uint32_t* b) {
    asm volatile("mma.sync.aligned.m16n8k16.row.col.f32.f16.f16.f32 "
                 "{%0,%1,%2,%3}, {%4,%5,%6,%7}, {%8,%9}, {%0,%1,%2,%3};"
                 : "+f"(c[0]), "+f"(c[1]), "+f"(c[2]), "+f"(c[3])
                 : "r"(a[0]), "r"(a[1]), "r"(a[2]), "r"(a[3]), "r"(b[0]), "r"(b[1]));
}

// ------------------------- [1] W build + wsq (fused) -------------------------
__global__ void __launch_bounds__(256) k_wbuild(const float* __restrict__ cw) {
    int c = blockIdx.y;
    int co = blockIdx.x * 4 + (threadIdx.x >> 6);
    int kp = threadIdx.x & 63;
    int k = kp ^ ((co & 7) << 3);
    const float* p = cw + ((size_t)co * 512 + c * 64 + k) * 9;
    float s = 0.f;
    #pragma unroll
    for (int tap = 0; tap < 9; tap++) {
        float w = p[tap];
        s += w * w;
        g_Ws[((size_t)(tap * 8 + c) * 512 + co) * 64 + kp] = __float2half_rn(w);
    }
    g_wsq[co * 512 + c * 64 + k] = s;
}

// ------------------------- [2] style -------------------------
__global__ void k_style(const float* __restrict__ wl, const float* __restrict__ aw,
                        const float* __restrict__ ab) {
    int w = blockIdx.x * 8 + (threadIdx.x >> 5), lane = threadIdx.x & 31;
    int b = w >> 9, ci = w & 511;
    const float* wlp = wl + b * 512;
    const float* awp = aw + (size_t)ci * 512;
    float s = 0.f;
    #pragma unroll 4
    for (int k = lane; k < 512; k += 32) s += wlp[k] * awp[k];
    #pragma unroll
    for (int o = 16; o; o >>= 1) s += __shfl_down_sync(0xffffffffu, s, o);
    if (lane == 0) g_style[w] = s * 0.04419417382415922f + ab[ci];
}

// ------------------------- [3] X prep -------------------------
__global__ void __launch_bounds__(256) k_xprep(const float* __restrict__ x) {
    const int b = blockIdx.z, c = blockIdx.y;
    const int tid = threadIdx.x;

    if (blockIdx.x == 16) {        // zero rows: ring (65/batch), pad (b==0), tail (b==15)
        int nrow = 65 + (b == 0 ? PADR : 0) + (b == 15 ? (NQPAD - NQV) : 0);
        for (int e = tid; e < nrow * 64; e += 256) {
            int ri = e >> 6, kp = e & 63;
            size_t prow;
            if (ri < 33) {
                prow = (size_t)c * NR + PADR + b * 1089 + 32 * 33 + ri;
            } else if (ri < 65) {
                prow = (size_t)c * NR + PADR + b * 1089 + (ri - 33) * 33 + 32;
            } else if (b == 0 && ri < 65 + PADR) {
                prow = (size_t)c * NR + (ri - 65);
            } else {
                int rj = ri - 65 - (b == 0 ? PADR : 0);
                prow = (size_t)c * NR + PADR + NQV + rj;
            }
            g_Xs[prow * 64 + kp] = __float2half_rn(0.f);
        }
        return;
    }

    __shared__ float t[64][65];
    const int px0 = blockIdx.x * 64;
    for (int e = tid; e < 4096; e += 256) {
        int ci_l = e >> 6, px = e & 63;
        t[ci_l][px] = x[(((size_t)b * 512 + c * 64 + ci_l) << 10) + px0 + px]
                    * g_style[b * 512 + c * 64 + ci_l];
    }
    __syncthreads();
    for (int e = tid; e < 2048; e += 256) {
        int px_l = e >> 5, kpp = e & 31;
        int pix = px0 + px_l;
        int m = pix >> 5, n = pix & 31;
        int q = b * 1089 + m * 33 + n;
        int k0 = (2 * kpp) ^ ((q & 7) << 3);
        size_t d = ((size_t)c * NR + PADR + q) * 64 + 2 * kpp;
        *(__half2*)&g_Xs[d] = __half2(__float2half_rn(t[k0][px_l]),
                                      __float2half_rn(t[k0 + 1][px_l]));
    }
}

// ------------------------- [4] GEMM (R13 exact: 128q x 128co, 2 CTA/SM, 3-stage) -------
__global__ void __launch_bounds__(256, 2) k_gemm() {
    extern __shared__ __align__(1024) char sm[];   // 3 stages x (A 16KB | B 16KB)
    const int tid = threadIdx.x;
    const int p = blockIdx.z, by = blockIdx.y;
    const int qbase = blockIdx.x * 128;
    const int ntap = c_nkb[p];
    const int NKB = ntap * 8;
    const int wid = tid >> 5, lane = tid & 31;
    const int wm = wid & 1, wn = wid >> 1;         // 2x4 warps -> 64q x 32co each
    const uint32_t sbase = smem_u32(sm);

    float acc[4][4][4];
    #pragma unroll
    for (int mt = 0; mt < 4; mt++)
        #pragma unroll
        for (int nt = 0; nt < 4; nt++)
            #pragma unroll
            for (int r = 0; r < 4; r++) acc[mt][nt][r] = 0.f;

    const int arow = lane & 15;
    const uint32_t acolhi = (uint32_t)(lane >> 4) << 4;
    uint32_t aoff[4];
    #pragma unroll
    for (int mt = 0; mt < 4; mt++) aoff[mt] = (wm * 64 + mt * 16 + arow) * 128;

    const int bnl = (lane & 7) + ((lane >> 4) << 3);
    const uint32_t bhi = (uint32_t)((lane >> 3) & 1) << 4;
    const uint32_t bsw = (uint32_t)(lane & 7) << 4;
    uint32_t boff[2];
    #pragma unroll
    for (int g = 0; g < 2; g++) boff[g] = (wn * 32 + g * 16 + bnl) * 128;

    auto stage_load = [&](int s, int kb) {
        int c = kb & 7, ti = kb >> 3;
        int off = c_off[p][ti], tap = c_taps[p][ti];
        const char* Ag = (const char*)(g_Xs + ((size_t)c * NR + PADR + qbase - off) * 64)
                       + tid * 64;
        const char* Bg = (const char*)(g_Ws + ((size_t)(tap * 8 + c) * 512 + by * 128) * 64)
                       + tid * 64;
        uint32_t sa = sbase + s * STG;
        #pragma unroll
        for (int i = 0; i < 4; i++) {
            cp16(sa + tid * 64 + i * 16,         Ag + i * 16);
            cp16(sa + 16384 + tid * 64 + i * 16, Bg + i * 16);
        }
        asm volatile("cp.async.commit_group;" ::: "memory");
    };

    stage_load(0, 0);
    if (NKB > 1) stage_load(1, 1);
    else asm volatile("cp.async.commit_group;" ::: "memory");

    for (int kb = 0; kb < NKB; kb++) {
        int s = kb % 3;
        asm volatile("cp.async.wait_group 1;" ::: "memory");
        __syncthreads();
        if (kb + 2 < NKB) stage_load((kb + 2) % 3, kb + 2);
        else asm volatile("cp.async.commit_group;" ::: "memory");

        int off = c_off[p][kb >> 3];
        uint32_t asw = (uint32_t)(((arow - off) & 7) << 4);
        uint32_t Abase = sbase + s * STG;
        uint32_t Bbase = Abase + 16384;
        #pragma unroll
        for (int ks = 0; ks < 4; ks++) {
            uint32_t A[4][4], Bf[4][2];
            uint32_t ak = (((uint32_t)ks << 5) | acolhi) ^ asw;
            #pragma unroll
            for (int mt = 0; mt < 4; mt++)
                ldsm4(A[mt][0], A[mt][1], A[mt][2], A[mt][3], Abase + aoff[mt] + ak);
            uint32_t bk = (((uint32_t)ks << 5) | bhi) ^ bsw;
            #pragma unroll
            for (int g = 0; g < 2; g++)
                ldsm4(Bf[2*g][0], Bf[2*g][1], Bf[2*g+1][0], Bf[2*g+1][1], Bbase + boff[g] + bk);
            #pragma unroll
            for (int mt = 0; mt < 4; mt++)
                #pragma unroll
                for (int nt = 0; nt < 4; nt++)
                    mma16816(acc[mt][nt], A[mt], Bf[nt]);
        }
    }

    #pragma unroll
    for (int mt = 0; mt < 4; mt++) {
        int r0 = qbase + wm * 64 + mt * 16 + (lane >> 2);
        #pragma unroll
        for (int nt = 0; nt < 4; nt++) {
            int co = by * 128 + wn * 32 + nt * 8 + ((lane & 3) << 1);
            if (r0 < NQV)
                *(__half2*)&g_yp[IDX(p, r0) * 512 + co] =
                    __floats2half2_rn(acc[mt][nt][0], acc[mt][nt][1]);
            if (r0 + 8 < NQV)
                *(__half2*)&g_yp[IDX(p, r0 + 8) * 512 + co] =
                    __floats2half2_rn(acc[mt][nt][2], acc[mt][nt][3]);
        }
    }
}

// ------------------------- [5] dcoef -------------------------
__global__ void k_dcoef() {
    int w = blockIdx.x * 8 + (threadIdx.x >> 5), lane = threadIdx.x & 31;
    int b = w >> 9, co = w & 511;
    float s = 0.f;
    #pragma unroll 4
    for (int ci = lane; ci < 512; ci += 32) {
        float st = g_style[b * 512 + ci];
        s += g_wsq[co * 512 + ci] * st * st;
    }
    #pragma unroll
    for (int o = 16; o; o >>= 1) s += __shfl_down_sync(0xffffffffu, s, o);
    if (lane == 0) g_dcoef[w] = rsqrtf(s + 1e-8f);
}

// ------------------------- [6] FIR + demod + noise + bias + lrelu + clamp ----------------
// ys[co][r*68 + cc]; fill at half2 granularity (co pairs) -> 128B/warp g_yp reads.
__global__ void __launch_bounds__(512) k_fir(const float* __restrict__ noise,
                                             const float* __restrict__ nstr,
                                             const float* __restrict__ bias,
                                             float* __restrict__ out) {
    extern __shared__ float ys[];                 // 32 co x RS
    const int u0 = blockIdx.x * 8;
    const int co0 = blockIdx.y * 32;
    const int b = blockIdx.z;
    const int tid = threadIdx.x;

    for (int e = tid; e < 11 * 67 * 16; e += 512) {
        int cl2 = e & 15, t = e >> 4;
        int cc = t % 67, r = t / 67;
        int rr = r + u0 - 1;
        int vccol = cc - 1;
        float v0f = 0.f, v1f = 0.f;
        if ((unsigned)rr <= 64u && (unsigned)vccol <= 64u) {
            int pp = ((rr & 1) << 1) | (vccol & 1);
            int q = b * 1089 + (rr >> 1) * 33 + (vccol >> 1);
            __half2 h2 = *(const __half2*)&g_yp[IDX(pp, q) * 512 + co0 + 2 * cl2];
            float2 f2 = __half22float2(h2);
            v0f = f2.x; v1f = f2.y;
        }
        int base = r * 68 + cc;
        ys[(2 * cl2) * RS + base]     = v0f;
        ys[(2 * cl2 + 1) * RS + base] = v1f;
    }
    __syncthreads();

    const int co_l = tid >> 4;                    // 0..31
    const int v0 = (tid & 15) * 4;                // lanes vary v -> coalesced
    const float fw[4] = {0.25f, 0.75f, 0.75f, 0.25f};
    const float dc = g_dcoef[b * 512 + co0 + co_l];
    const float ns = nstr[0];
    const float bi = bias[co0 + co_l];
    const float4* yrow = (const float4*)(ys + co_l * RS);

    float rs[11][4];
    #pragma unroll
    for (int r = 0; r < 11; r++) {
        float4 a = yrow[(r * 68 + v0) >> 2];
        float4 bq = yrow[(r * 68 + v0 + 4) >> 2];
        float w[8] = {a.x, a.y, a.z, a.w, bq.x, bq.y, bq.z, bq.w};
        #pragma unroll
        for (int j = 0; j < 4; j++)
            rs[r][j] = fmaf(fw[0], w[j], fmaf(fw[1], w[j+1],
                       fmaf(fw[2], w[j+2], fw[3] * w[j+3])));
    }

    #pragma unroll
    for (int ul = 0; ul < 8; ul++) {
        const int u = u0 + ul;
        const float4 nz = *(const float4*)&noise[(b << 12) + u * 64 + v0];
        const float nzv[4] = {nz.x, nz.y, nz.z, nz.w};
        float4 o4;
        float* op = &o4.x;
        #pragma unroll
        for (int j = 0; j < 4; j++) {
            float accv = fmaf(fw[0], rs[ul][j], fmaf(fw[1], rs[ul+1][j],
                         fmaf(fw[2], rs[ul+2][j], fw[3] * rs[ul+3][j])));
            float val = fmaf(nzv[j], ns, accv * dc) + bi;
            val = (val > 0.f ? val : 0.2f * val) * 1.4142135623730951f;
            val = fminf(fmaxf(val, -256.f), 256.f);
            op[j] = val;
        }
        *(float4*)&out[(((size_t)b * 512 + co0 + co_l) * 64 + u) * 64 + v0] = o4;
    }
}

// ------------------------- launch -------------------------
extern "C" void kernel_launch(void* const* d_in, const int* in_sizes, int n_in,
                              void* d_out, int out_size) {
    const float* x     = (const float*)d_in[0];
    const float* wl    = (const float*)d_in[1];
    const float* aw    = (const float*)d_in[2];
    const float* ab    = (const float*)d_in[3];
    const float* cw    = (const float*)d_in[4];
    const float* noise = (const float*)d_in[5];
    const float* nstr  = (const float*)d_in[6];
    const float* bias  = (const float*)d_in[7];
    float* out = (float*)d_out;

    cudaFuncSetAttribute(k_gemm, cudaFuncAttributeMaxDynamicSharedMemorySize, 3 * STG);
    cudaFuncSetAttribute(k_fir, cudaFuncAttributeMaxDynamicSharedMemorySize, FIRSM);

    k_wbuild<<<dim3(128, 8), 256>>>(cw);                    // 1 (wsq fused)
    k_style<<<1024, 256>>>(wl, aw, ab);                     // 2
    k_xprep<<<dim3(17, 8, B_), 256>>>(x);                   // 3
    k_gemm<<<dim3(QT, 4, 4), 256, 3 * STG>>>();             // 4  <- profiled slot
    k_dcoef<<<1024, 256>>>();                               // 5
    k_fir<<<dim3(8, 16, B_), 512, FIRSM>>>(noise, nstr, bias, out);  // 6
}